// round 7
// baseline (speedup 1.0000x reference)
#include <cuda_runtime.h>
#include <cuda_bf16.h>
#include <stdint.h>

// Problem constants
#define BATCH   4
#define HEADS   16
#define SEQ     2048
#define DK      64
#define DMODEL  1024
#define NTOK    (BATCH * SEQ)            // 8192
#define BH      (BATCH * HEADS)          // 64
#define CSTRIDE ((size_t)BH * SEQ * DK)  // elements per Q/K/V plane

// Scratch (device globals: cudaMalloc is forbidden)
__device__ __nv_bfloat16 g_qkvh[3 * BH * SEQ * DK];      // bf16-hi [c][bh][s][dk]
__device__ __nv_bfloat16 g_qkvl[3 * BH * SEQ * DK];      // bf16-lo
__device__ __nv_bfloat16 g_xhi[NTOK * DMODEL];
__device__ __nv_bfloat16 g_xlo[NTOK * DMODEL];
__device__ __nv_bfloat16 g_wqhi[3 * DMODEL * DMODEL];
__device__ __nv_bfloat16 g_wqlo[3 * DMODEL * DMODEL];
__device__ __nv_bfloat16 g_hhi[NTOK * DMODEL];           // attention out hi
__device__ __nv_bfloat16 g_hlo[NTOK * DMODEL];           // attention out lo
__device__ __nv_bfloat16 g_wohi[DMODEL * DMODEL];
__device__ __nv_bfloat16 g_wolo[DMODEL * DMODEL];

// ---------------------------------------------------------------------------
// Warp MMA + async-copy helpers (sm_80+ instructions only)
// ---------------------------------------------------------------------------
__device__ __forceinline__ uint32_t smem_u32(const void* p) {
    uint32_t a;
    asm("{ .reg .u64 t; cvta.to.shared.u64 t, %1; cvt.u32.u64 %0, t; }"
        : "=r"(a) : "l"(p));
    return a;
}
__device__ __forceinline__ void ldsm_x4(uint32_t& r0, uint32_t& r1,
                                        uint32_t& r2, uint32_t& r3, uint32_t addr) {
    asm volatile("ldmatrix.sync.aligned.m8n8.x4.shared.b16 {%0,%1,%2,%3}, [%4];"
                 : "=r"(r0), "=r"(r1), "=r"(r2), "=r"(r3) : "r"(addr));
}
__device__ __forceinline__ void ldsm_x4t(uint32_t& r0, uint32_t& r1,
                                         uint32_t& r2, uint32_t& r3, uint32_t addr) {
    asm volatile("ldmatrix.sync.aligned.m8n8.x4.trans.shared.b16 {%0,%1,%2,%3}, [%4];"
                 : "=r"(r0), "=r"(r1), "=r"(r2), "=r"(r3) : "r"(addr));
}
__device__ __forceinline__ void mma_bf16(float* c, const uint32_t* a, const uint32_t* b) {
    asm volatile("mma.sync.aligned.m16n8k16.row.col.f32.bf16.bf16.f32 "
                 "{%0,%1,%2,%3}, {%4,%5,%6,%7}, {%8,%9}, {%0,%1,%2,%3};"
                 : "+f"(c[0]), "+f"(c[1]), "+f"(c[2]), "+f"(c[3])
                 : "r"(a[0]), "r"(a[1]), "r"(a[2]), "r"(a[3]),
                   "r"(b[0]), "r"(b[1]));
}
__device__ __forceinline__ uint32_t pack_bf16(float a, float b) {
    __nv_bfloat162 h;
    h.x = __float2bfloat16_rn(a);
    h.y = __float2bfloat16_rn(b);
    return *(uint32_t*)&h;
}
__device__ __forceinline__ void cp16(uint32_t s, const void* g) {
    asm volatile("cp.async.cg.shared.global [%0], [%1], 16;" :: "r"(s), "l"(g));
}
#define CP_COMMIT() asm volatile("cp.async.commit_group;")
#define CP_WAIT1()  asm volatile("cp.async.wait_group 1;")

// ---------------------------------------------------------------------------
// fp32 -> bf16 hi/lo split
// ---------------------------------------------------------------------------
__global__ __launch_bounds__(256)
void split_kernel(const float4* __restrict__ src,
                  __nv_bfloat16* __restrict__ hi,
                  __nv_bfloat16* __restrict__ lo, int n4)
{
    int i = blockIdx.x * blockDim.x + threadIdx.x;
    if (i >= n4) return;
    float4 v = src[i];
    float f[4] = {v.x, v.y, v.z, v.w};
    __nv_bfloat16 h[4], l[4];
#pragma unroll
    for (int j = 0; j < 4; ++j) {
        h[j] = __float2bfloat16_rn(f[j]);
        l[j] = __float2bfloat16_rn(f[j] - __bfloat162float(h[j]));
    }
    __nv_bfloat162 h01; h01.x = h[0]; h01.y = h[1];
    __nv_bfloat162 h23; h23.x = h[2]; h23.y = h[3];
    __nv_bfloat162 l01; l01.x = l[0]; l01.y = l[1];
    __nv_bfloat162 l23; l23.x = l[2]; l23.y = l[3];
    *(__nv_bfloat162*)(hi + 4 * (size_t)i)     = h01;
    *(__nv_bfloat162*)(hi + 4 * (size_t)i + 2) = h23;
    *(__nv_bfloat162*)(lo + 4 * (size_t)i)     = l01;
    *(__nv_bfloat162*)(lo + 4 * (size_t)i + 2) = l23;
}

// ---------------------------------------------------------------------------
// Split-bf16 GEMM on HMMA. 512 threads = 16 warps (4m x 4n), warp tile 32x32.
// 3-stage cp.async ring, ONE barrier per k-chunk (BK=32).
// C[M,N] = A[M,K] * B[N,K]^T, K = 1024.
// mode 0: fp32 store to C.  mode 1: split-store to g_qkvh/g_qkvl planes
// (Q plane pre-scaled by 1/sqrt(DK)).
// ---------------------------------------------------------------------------
#define BKS      32
#define NKI      (DMODEL / BKS)         // 32
#define PLANE_B  (128 * 80)             // 10240 bytes (rows padded to 80 B)
#define STAGE_B4 (4 * PLANE_B)          // Ah, Al, Bh, Bl
#define NSTG     3
#define GSMEM    (NSTG * STAGE_B4)      // 122880 bytes

__global__ __launch_bounds__(512, 1)
void gemm_mma_kernel(const __nv_bfloat16* __restrict__ Ahi,
                     const __nv_bfloat16* __restrict__ Alo,
                     const __nv_bfloat16* __restrict__ Bhi,
                     const __nv_bfloat16* __restrict__ Blo,
                     float* __restrict__ C, int N, int mode)
{
    extern __shared__ char smem[];
    const uint32_t sbase = smem_u32(smem);
    const int tid  = threadIdx.x;
    const int wid  = tid >> 5;
    const int lane = tid & 31;
    const int wm   = wid >> 2;          // 0..3 (32-row slab)
    const int wn   = wid & 3;           // 0..3 (32-col slab)
    const int m0   = blockIdx.y * 128;
    const int n0   = blockIdx.x * 128;
    const int K    = DMODEL;

    const __nv_bfloat16* gsrc[4] = {
        Ahi + (size_t)m0 * K, Alo + (size_t)m0 * K,
        Bhi + (size_t)n0 * K, Blo + (size_t)n0 * K };

    // async stage issue: 4 x 16B per thread (512 threads cover 4 planes)
    const int r_ = tid >> 2;            // 0..127
    const int c_ = tid & 3;             // 16B chunk in 64B row
    auto issue_stage = [&](int buf, int kc) {
        const uint32_t dst = sbase + buf * STAGE_B4 + r_ * 80 + c_ * 16;
        const size_t goff = (size_t)r_ * K + kc + c_ * 8;
#pragma unroll
        for (int p = 0; p < 4; ++p)
            cp16(dst + p * PLANE_B, gsrc[p] + goff);
    };

    issue_stage(0, 0);      CP_COMMIT();
    issue_stage(1, BKS);    CP_COMMIT();

    float acc[2][4][4];
#pragma unroll
    for (int mi = 0; mi < 2; ++mi)
#pragma unroll
        for (int nj = 0; nj < 4; ++nj)
#pragma unroll
            for (int q = 0; q < 4; ++q) acc[mi][nj][q] = 0.0f;

    for (int kt = 0; kt < NKI; ++kt) {
        CP_WAIT1();            // chunk kt has arrived
        __syncthreads();       // all warps finished compute kt-1
        if (kt + 2 < NKI) {    // refill the buffer consumed at kt-1
            issue_stage((kt + 2) % NSTG, (kt + 2) * BKS);
            CP_COMMIT();
        }

        const uint32_t sb = sbase + (kt % NSTG) * STAGE_B4;
#pragma unroll
        for (int ks = 0; ks < 2; ++ks) {
            uint32_t ah[2][4], al[2][4], bh[4][2], bl[4][2];
#pragma unroll
            for (int mi = 0; mi < 2; ++mi) {
                const int row = wm * 32 + mi * 16 + (lane & 15);
                const uint32_t a = sb + row * 80 + ks * 32 + (lane >> 4) * 16;
                ldsm_x4(ah[mi][0], ah[mi][1], ah[mi][2], ah[mi][3], a);
                ldsm_x4(al[mi][0], al[mi][1], al[mi][2], al[mi][3], a + PLANE_B);
            }
#pragma unroll
            for (int p2 = 0; p2 < 2; ++p2) {   // nj pair: 2*p2, 2*p2+1
                const int row = wn * 32 + p2 * 16 + (lane & 15);
                const uint32_t a = sb + 2 * PLANE_B + row * 80
                                 + ks * 32 + (lane >> 4) * 16;
                uint32_t r0, r1, r2, r3;
                ldsm_x4(r0, r1, r2, r3, a);
                bh[2 * p2][0] = r0; bh[2 * p2][1] = r2;
                bh[2 * p2 + 1][0] = r1; bh[2 * p2 + 1][1] = r3;
                ldsm_x4(r0, r1, r2, r3, a + PLANE_B);
                bl[2 * p2][0] = r0; bl[2 * p2][1] = r2;
                bl[2 * p2 + 1][0] = r1; bl[2 * p2 + 1][1] = r3;
            }
#pragma unroll
            for (int mi = 0; mi < 2; ++mi)
#pragma unroll
                for (int nj = 0; nj < 4; ++nj) {
                    mma_bf16(acc[mi][nj], ah[mi], bh[nj]);
                    mma_bf16(acc[mi][nj], ah[mi], bl[nj]);
                    mma_bf16(acc[mi][nj], al[mi], bh[nj]);
                }
        }
    }

#pragma unroll
    for (int mi = 0; mi < 2; ++mi)
#pragma unroll
        for (int nj = 0; nj < 4; ++nj) {
            const int mrow = m0 + wm * 32 + mi * 16 + (lane >> 2);
            const int ncol = n0 + wn * 32 + nj * 8 + (lane & 3) * 2;
            if (mode == 0) {
                *(float2*)(C + (size_t)mrow * N + ncol) =
                    make_float2(acc[mi][nj][0], acc[mi][nj][1]);
                *(float2*)(C + (size_t)(mrow + 8) * N + ncol) =
                    make_float2(acc[mi][nj][2], acc[mi][nj][3]);
            } else {
                const int cc = ncol >> 10;
                const int h  = (ncol >> 6) & (HEADS - 1);
                const int dk = ncol & (DK - 1);
                const float scl = (cc == 0) ? 0.125f : 1.0f;
#pragma unroll
                for (int half = 0; half < 2; ++half) {
                    const int m = mrow + half * 8;
                    const int b = m >> 11;
                    const int s = m & (SEQ - 1);
                    const size_t off = (size_t)cc * CSTRIDE
                        + ((size_t)(b * HEADS + h) * SEQ + s) * DK + dk;
                    float v0 = acc[mi][nj][half * 2]     * scl;
                    float v1 = acc[mi][nj][half * 2 + 1] * scl;
                    __nv_bfloat162 hi2, lo2;
                    hi2.x = __float2bfloat16_rn(v0);
                    hi2.y = __float2bfloat16_rn(v1);
                    lo2.x = __float2bfloat16_rn(v0 - __bfloat162float(hi2.x));
                    lo2.y = __float2bfloat16_rn(v1 - __bfloat162float(hi2.y));
                    *(__nv_bfloat162*)(g_qkvh + off) = hi2;
                    *(__nv_bfloat162*)(g_qkvl + off) = lo2;
                }
            }
        }
}

// ---------------------------------------------------------------------------
// Causal flash attention on HMMA, split-bf16 (3 MMA terms per product).
// Grid: (SEQ/128, BH). Block: 256 threads = 8 warps; warp owns 16 q-rows.
// KV tiles of 64 keys; next tile register-prefetched during compute.
// ---------------------------------------------------------------------------
#define ASTR   144                    // padded row pitch bytes (64 bf16 + 8 pad)
#define A_QH   0
#define A_QL   (128 * ASTR)
#define A_KH   (2 * 128 * ASTR)
#define A_KL   (A_KH + 64 * ASTR)
#define A_VH   (A_KL + 64 * ASTR)
#define A_VL   (A_VH + 64 * ASTR)
#define A_TOTAL (A_VL + 64 * ASTR)    // 73728 bytes

__global__ __launch_bounds__(256, 1)
void attn_mma_kernel()
{
    extern __shared__ char smem[];
    const uint32_t sb = smem_u32(smem);
    const int tid  = threadIdx.x;
    const int w    = tid >> 5;
    const int lane = tid & 31;
    const int qt   = blockIdx.x;          // 128-row q tile
    const int bh   = blockIdx.y;
    const int q0   = qt * 128;

    const __nv_bfloat16* Qh = g_qkvh + ((size_t)bh * SEQ + q0) * DK;
    const __nv_bfloat16* Ql = g_qkvl + ((size_t)bh * SEQ + q0) * DK;
    const __nv_bfloat16* Kh = g_qkvh + CSTRIDE     + (size_t)bh * SEQ * DK;
    const __nv_bfloat16* Kl = g_qkvl + CSTRIDE     + (size_t)bh * SEQ * DK;
    const __nv_bfloat16* Vh = g_qkvh + 2 * CSTRIDE + (size_t)bh * SEQ * DK;
    const __nv_bfloat16* Vl = g_qkvl + 2 * CSTRIDE + (size_t)bh * SEQ * DK;

    const int r_ = tid >> 3;              // 0..31
    const int c_ = tid & 7;               // 16B chunk

    // Load Q tile (128 x 64) hi/lo + KV tile 0 into smem
#pragma unroll
    for (int t = 0; t < 4; ++t) {
        const int row = r_ + t * 32;
        *(uint4*)(smem + A_QH + row * ASTR + c_ * 16) =
            *(const uint4*)(Qh + (size_t)row * DK + c_ * 8);
        *(uint4*)(smem + A_QL + row * ASTR + c_ * 16) =
            *(const uint4*)(Ql + (size_t)row * DK + c_ * 8);
    }
#pragma unroll
    for (int t = 0; t < 2; ++t) {
        const int row = r_ + t * 32;
        const size_t g = (size_t)row * DK + c_ * 8;
        const int so = row * ASTR + c_ * 16;
        *(uint4*)(smem + A_KH + so) = *(const uint4*)(Kh + g);
        *(uint4*)(smem + A_KL + so) = *(const uint4*)(Kl + g);
        *(uint4*)(smem + A_VH + so) = *(const uint4*)(Vh + g);
        *(uint4*)(smem + A_VL + so) = *(const uint4*)(Vl + g);
    }
    __syncthreads();

    // Q fragments (registers, whole kernel)
    uint32_t qfh[4][4], qfl[4][4];
#pragma unroll
    for (int kk = 0; kk < 4; ++kk) {
        const int row = w * 16 + (lane & 15);
        const uint32_t a = sb + A_QH + row * ASTR + kk * 32 + (lane >> 4) * 16;
        ldsm_x4(qfh[kk][0], qfh[kk][1], qfh[kk][2], qfh[kk][3], a);
        ldsm_x4(qfl[kk][0], qfl[kk][1], qfl[kk][2], qfl[kk][3],
                a + (A_QL - A_QH));
    }

    float o[8][4];
#pragma unroll
    for (int nj = 0; nj < 8; ++nj)
#pragma unroll
        for (int q = 0; q < 4; ++q) o[nj][q] = 0.0f;
    float mA = -1e30f, mB = -1e30f, lA = 0.0f, lB = 0.0f;

    const int nkt = 2 * qt + 2;
    for (int kt = 0; kt < nkt; ++kt) {
        // Prefetch next KV tile into registers (latency hidden by compute)
        uint4 pf[8];
        const bool havepf = (kt + 1 < nkt);
        if (havepf) {
#pragma unroll
            for (int t = 0; t < 2; ++t) {
                const int row = r_ + t * 32;
                const size_t g = (size_t)((kt + 1) * 64 + row) * DK + c_ * 8;
                pf[t * 4 + 0] = *(const uint4*)(Kh + g);
                pf[t * 4 + 1] = *(const uint4*)(Kl + g);
                pf[t * 4 + 2] = *(const uint4*)(Vh + g);
                pf[t * 4 + 3] = *(const uint4*)(Vl + g);
            }
        }

        // Warps 0-3 (rows q0..q0+63) fully masked on the last diagonal tile
        if (!(kt == 2 * qt + 1 && w < 4)) {
            // ---- S = Q K^T (3 terms) ----
            float s[8][4];
#pragma unroll
            for (int nj = 0; nj < 8; ++nj)
#pragma unroll
                for (int q = 0; q < 4; ++q) s[nj][q] = 0.0f;

#pragma unroll
            for (int kk = 0; kk < 4; ++kk) {
                uint32_t bkh[8][2], bkl[8][2];
#pragma unroll
                for (int p2 = 0; p2 < 4; ++p2) {
                    const uint32_t a = sb + A_KH + (p2 * 16 + (lane & 15)) * ASTR
                                     + kk * 32 + (lane >> 4) * 16;
                    uint32_t r0, r1, r2, r3;
                    ldsm_x4(r0, r1, r2, r3, a);
                    bkh[2 * p2][0] = r0; bkh[2 * p2][1] = r2;
                    bkh[2 * p2 + 1][0] = r1; bkh[2 * p2 + 1][1] = r3;
                    ldsm_x4(r0, r1, r2, r3, a + (A_KL - A_KH));
                    bkl[2 * p2][0] = r0; bkl[2 * p2][1] = r2;
                    bkl[2 * p2 + 1][0] = r1; bkl[2 * p2 + 1][1] = r3;
                }
#pragma unroll
                for (int nj = 0; nj < 8; ++nj) {
                    mma_bf16(s[nj], qfh[kk], bkh[nj]);
                    mma_bf16(s[nj], qfh[kk], bkl[nj]);
                    mma_bf16(s[nj], qfl[kk], bkh[nj]);
                }
            }

            // ---- causal mask (diagonal tiles only) ----
            if (kt >= 2 * qt) {
                const int rowA = q0 + w * 16 + (lane >> 2);
                const int k0   = kt * 64;
#pragma unroll
                for (int nj = 0; nj < 8; ++nj) {
                    const int c0 = k0 + nj * 8 + (lane & 3) * 2;
                    if (c0 > rowA)     s[nj][0] = -1e30f;
                    if (c0 + 1 > rowA) s[nj][1] = -1e30f;
                    if (c0 > rowA + 8)     s[nj][2] = -1e30f;
                    if (c0 + 1 > rowA + 8) s[nj][3] = -1e30f;
                }
            }

            // ---- online softmax ----
            float tmA = -1e30f, tmB = -1e30f;
#pragma unroll
            for (int nj = 0; nj < 8; ++nj) {
                tmA = fmaxf(tmA, fmaxf(s[nj][0], s[nj][1]));
                tmB = fmaxf(tmB, fmaxf(s[nj][2], s[nj][3]));
            }
            tmA = fmaxf(tmA, __shfl_xor_sync(0xffffffffu, tmA, 1));
            tmA = fmaxf(tmA, __shfl_xor_sync(0xffffffffu, tmA, 2));
            tmB = fmaxf(tmB, __shfl_xor_sync(0xffffffffu, tmB, 1));
            tmB = fmaxf(tmB, __shfl_xor_sync(0xffffffffu, tmB, 2));
            const float mnA = fmaxf(mA, tmA);
            const float mnB = fmaxf(mB, tmB);
            const float fA = __expf(mA - mnA);
            const float fB = __expf(mB - mnB);
            mA = mnA; mB = mnB;

            float rsA = 0.0f, rsB = 0.0f;
#pragma unroll
            for (int nj = 0; nj < 8; ++nj) {
                s[nj][0] = __expf(s[nj][0] - mnA);
                s[nj][1] = __expf(s[nj][1] - mnA);
                s[nj][2] = __expf(s[nj][2] - mnB);
                s[nj][3] = __expf(s[nj][3] - mnB);
                rsA += s[nj][0] + s[nj][1];
                rsB += s[nj][2] + s[nj][3];
            }
            rsA += __shfl_xor_sync(0xffffffffu, rsA, 1);
            rsA += __shfl_xor_sync(0xffffffffu, rsA, 2);
            rsB += __shfl_xor_sync(0xffffffffu, rsB, 1);
            rsB += __shfl_xor_sync(0xffffffffu, rsB, 2);
            lA = lA * fA + rsA;
            lB = lB * fB + rsB;
#pragma unroll
            for (int nj = 0; nj < 8; ++nj) {
                o[nj][0] *= fA; o[nj][1] *= fA;
                o[nj][2] *= fB; o[nj][3] *= fB;
            }

            // ---- O += P V (3 terms) ----
#pragma unroll
            for (int kk = 0; kk < 4; ++kk) {
                const int j0 = 2 * kk, j1 = 2 * kk + 1;
                uint32_t ph[4], pl[4];
                ph[0] = pack_bf16(s[j0][0], s[j0][1]);
                ph[1] = pack_bf16(s[j0][2], s[j0][3]);
                ph[2] = pack_bf16(s[j1][0], s[j1][1]);
                ph[3] = pack_bf16(s[j1][2], s[j1][3]);
                {
                    __nv_bfloat162* hp;
                    float l0, l1;
                    hp = (__nv_bfloat162*)&ph[0];
                    l0 = s[j0][0] - __bfloat162float(hp->x);
                    l1 = s[j0][1] - __bfloat162float(hp->y);
                    pl[0] = pack_bf16(l0, l1);
                    hp = (__nv_bfloat162*)&ph[1];
                    l0 = s[j0][2] - __bfloat162float(hp->x);
                    l1 = s[j0][3] - __bfloat162float(hp->y);
                    pl[1] = pack_bf16(l0, l1);
                    hp = (__nv_bfloat162*)&ph[2];
                    l0 = s[j1][0] - __bfloat162float(hp->x);
                    l1 = s[j1][1] - __bfloat162float(hp->y);
                    pl[2] = pack_bf16(l0, l1);
                    hp = (__nv_bfloat162*)&ph[3];
                    l0 = s[j1][2] - __bfloat162float(hp->x);
                    l1 = s[j1][3] - __bfloat162float(hp->y);
                    pl[3] = pack_bf16(l0, l1);
                }
#pragma unroll
                for (int p2 = 0; p2 < 4; ++p2) {
                    const uint32_t a = sb + A_VH
                        + (kk * 16 + (lane & 7) + ((lane >> 3) & 1) * 8) * ASTR
                        + p2 * 32 + (lane >> 4) * 16;
                    uint32_t r0, r1, r2, r3;
                    ldsm_x4t(r0, r1, r2, r3, a);
                    uint32_t bvh0[2] = {r0, r1}, bvh1[2] = {r2, r3};
                    ldsm_x4t(r0, r1, r2, r3, a + (A_VL - A_VH));
                    uint32_t bvl0[2] = {r0, r1}, bvl1[2] = {r2, r3};
                    mma_bf16(o[2 * p2],     ph, bvh0);
                    mma_bf16(o[2 * p2],     ph, bvl0);
                    mma_bf16(o[2 * p2],     pl, bvh0);
                    mma_bf16(o[2 * p2 + 1], ph, bvh1);
                    mma_bf16(o[2 * p2 + 1], ph, bvl1);
                    mma_bf16(o[2 * p2 + 1], pl, bvh1);
                }
            }
        }

        if (havepf) {
            __syncthreads();   // all warps done reading current KV tile
#pragma unroll
            for (int t = 0; t < 2; ++t) {
                const int row = r_ + t * 32;
                const int so = row * ASTR + c_ * 16;
                *(uint4*)(smem + A_KH + so) = pf[t * 4 + 0];
                *(uint4*)(smem + A_KL + so) = pf[t * 4 + 1];
                *(uint4*)(smem + A_VH + so) = pf[t * 4 + 2];
                *(uint4*)(smem + A_VL + so) = pf[t * 4 + 3];
            }
            __syncthreads();
        }
    }

    // ---- normalize + split-store heads [b*S+s][h*DK+dk] ----
    const int b = bh >> 4;
    const int h = bh & 15;
    const float iA = 1.0f / lA;
    const float iB = 1.0f / lB;
    const int rowA = q0 + w * 16 + (lane >> 2);
#pragma unroll
    for (int nj = 0; nj < 8; ++nj) {
        const int col = h * DK + nj * 8 + (lane & 3) * 2;
        float v0 = o[nj][0] * iA, v1 = o[nj][1] * iA;
        float v2 = o[nj][2] * iB, v3 = o[nj][3] * iB;
        __nv_bfloat162 hi2, lo2;
        size_t off = (size_t)(b * SEQ + rowA) * DMODEL + col;
        hi2.x = __float2bfloat16_rn(v0);
        hi2.y = __float2bfloat16_rn(v1);
        lo2.x = __float2bfloat16_rn(v0 - __bfloat162float(hi2.x));
        lo2.y = __float2bfloat16_rn(v1 - __bfloat162float(hi2.y));
        *(__nv_bfloat162*)(g_hhi + off) = hi2;
        *(__nv_bfloat162*)(g_hlo + off) = lo2;
        off += 8 * DMODEL;
        hi2.x = __float2bfloat16_rn(v2);
        hi2.y = __float2bfloat16_rn(v3);
        lo2.x = __float2bfloat16_rn(v2 - __bfloat162float(hi2.x));
        lo2.y = __float2bfloat16_rn(v3 - __bfloat162float(hi2.y));
        *(__nv_bfloat162*)(g_hhi + off) = hi2;
        *(__nv_bfloat162*)(g_hlo + off) = lo2;
    }
}

// ---------------------------------------------------------------------------
extern "C" void kernel_launch(void* const* d_in, const int* in_sizes, int n_in,
                              void* d_out, int out_size)
{
    const float* x     = (const float*)d_in[0];
    const float* w_qkv = (const float*)d_in[1];
    const float* w_o   = (const float*)d_in[2];
    float* out = (float*)d_out;

    __nv_bfloat16 *xhi, *xlo, *wqhi, *wqlo, *hhi, *hlo, *wohi, *wolo;
    cudaGetSymbolAddress((void**)&xhi,  g_xhi);
    cudaGetSymbolAddress((void**)&xlo,  g_xlo);
    cudaGetSymbolAddress((void**)&wqhi, g_wqhi);
    cudaGetSymbolAddress((void**)&wqlo, g_wqlo);
    cudaGetSymbolAddress((void**)&hhi,  g_hhi);
    cudaGetSymbolAddress((void**)&hlo,  g_hlo);
    cudaGetSymbolAddress((void**)&wohi, g_wohi);
    cudaGetSymbolAddress((void**)&wolo, g_wolo);

    cudaFuncSetAttribute(gemm_mma_kernel,
                         cudaFuncAttributeMaxDynamicSharedMemorySize, GSMEM);
    cudaFuncSetAttribute(attn_mma_kernel,
                         cudaFuncAttributeMaxDynamicSharedMemorySize, A_TOTAL);

    // 1) split inputs
    split_kernel<<<NTOK * DMODEL / 4 / 256, 256>>>((const float4*)x, xhi, xlo,
                                                   NTOK * DMODEL / 4);
    split_kernel<<<3 * DMODEL * DMODEL / 4 / 256, 256>>>((const float4*)w_qkv, wqhi, wqlo,
                                                         3 * DMODEL * DMODEL / 4);
    split_kernel<<<DMODEL * DMODEL / 4 / 256, 256>>>((const float4*)w_o, wohi, wolo,
                                                     DMODEL * DMODEL / 4);

    // 2) QKV projection -> bf16 hi/lo per-head planes (Q pre-scaled)
    gemm_mma_kernel<<<dim3(24, 64), 512, GSMEM>>>(xhi, xlo, wqhi, wqlo,
                                                  nullptr, 3 * DMODEL, 1);
    // 3) causal flash attention (HMMA split-bf16) -> heads hi/lo
    attn_mma_kernel<<<dim3(SEQ / 128, BH), 256, A_TOTAL>>>();

    // 4) output projection
    gemm_mma_kernel<<<dim3(8, 64), 512, GSMEM>>>(hhi, hlo, wohi, wolo,
                                                 out, DMODEL, 0);
}

// round 8
// speedup vs baseline: 1.3941x; 1.3941x over previous
#include <cuda_runtime.h>
#include <cuda_fp16.h>
#include <stdint.h>

// Problem constants
#define BATCH   4
#define HEADS   16
#define SEQ     2048
#define DK      64
#define DMODEL  1024
#define NTOK    (BATCH * SEQ)            // 8192
#define BH      (BATCH * HEADS)          // 64
#define PSTRIDE ((size_t)BH * SEQ * DK)  // elements per plane

// Scratch (device globals: cudaMalloc is forbidden)
__device__ __half g_xhi[NTOK * DMODEL];
__device__ __half g_xlo[NTOK * DMODEL];
__device__ __half g_wq [3 * DMODEL * DMODEL];
__device__ __half g_wo [DMODEL * DMODEL];
__device__ __half g_qh [BH * SEQ * DK];          // Q hi (pre-scaled 1/8)
__device__ __half g_ql [BH * SEQ * DK];          // Q lo
__device__ __half g_ks [BH * SEQ * DK];          // K single fp16
__device__ __half g_vs [BH * SEQ * DK];          // V single fp16
__device__ __half g_hhi[NTOK * DMODEL];          // heads hi
__device__ __half g_hlo[NTOK * DMODEL];          // heads lo

// ---------------------------------------------------------------------------
// Warp MMA + async-copy helpers (sm_80+ instructions only)
// ---------------------------------------------------------------------------
__device__ __forceinline__ uint32_t smem_u32(const void* p) {
    uint32_t a;
    asm("{ .reg .u64 t; cvta.to.shared.u64 t, %1; cvt.u32.u64 %0, t; }"
        : "=r"(a) : "l"(p));
    return a;
}
__device__ __forceinline__ void ldsm_x4(uint32_t& r0, uint32_t& r1,
                                        uint32_t& r2, uint32_t& r3, uint32_t addr) {
    asm volatile("ldmatrix.sync.aligned.m8n8.x4.shared.b16 {%0,%1,%2,%3}, [%4];"
                 : "=r"(r0), "=r"(r1), "=r"(r2), "=r"(r3) : "r"(addr));
}
__device__ __forceinline__ void ldsm_x4t(uint32_t& r0, uint32_t& r1,
                                         uint32_t& r2, uint32_t& r3, uint32_t addr) {
    asm volatile("ldmatrix.sync.aligned.m8n8.x4.trans.shared.b16 {%0,%1,%2,%3}, [%4];"
                 : "=r"(r0), "=r"(r1), "=r"(r2), "=r"(r3) : "r"(addr));
}
__device__ __forceinline__ void mma_f16(float* c, const uint32_t* a, const uint32_t* b) {
    asm volatile("mma.sync.aligned.m16n8k16.row.col.f32.f16.f16.f32 "
                 "{%0,%1,%2,%3}, {%4,%5,%6,%7}, {%8,%9}, {%0,%1,%2,%3};"
                 : "+f"(c[0]), "+f"(c[1]), "+f"(c[2]), "+f"(c[3])
                 : "r"(a[0]), "r"(a[1]), "r"(a[2]), "r"(a[3]),
                   "r"(b[0]), "r"(b[1]));
}
__device__ __forceinline__ uint32_t pack_f16(float a, float b) {
    __half2 h = __floats2half2_rn(a, b);
    return *(uint32_t*)&h;
}
__device__ __forceinline__ void cp16(uint32_t s, const void* g) {
    asm volatile("cp.async.cg.shared.global [%0], [%1], 16;" :: "r"(s), "l"(g));
}
#define CP_COMMIT() asm volatile("cp.async.commit_group;")
#define CP_WAIT1()  asm volatile("cp.async.wait_group 1;")

// ---------------------------------------------------------------------------
// fp32 -> fp16 hi/lo split, and fp32 -> fp16 round
// ---------------------------------------------------------------------------
__global__ __launch_bounds__(256)
void split_f16_kernel(const float4* __restrict__ src,
                      __half* __restrict__ hi, __half* __restrict__ lo, int n4)
{
    int i = blockIdx.x * blockDim.x + threadIdx.x;
    if (i >= n4) return;
    float4 v = src[i];
    float f[4] = {v.x, v.y, v.z, v.w};
    __half h[4];
    float  l[4];
#pragma unroll
    for (int j = 0; j < 4; ++j) {
        h[j] = __float2half_rn(f[j]);
        l[j] = f[j] - __half2float(h[j]);
    }
    __half2 h01; h01.x = h[0]; h01.y = h[1];
    __half2 h23; h23.x = h[2]; h23.y = h[3];
    *(__half2*)(hi + 4 * (size_t)i)     = h01;
    *(__half2*)(hi + 4 * (size_t)i + 2) = h23;
    *(__half2*)(lo + 4 * (size_t)i)     = __floats2half2_rn(l[0], l[1]);
    *(__half2*)(lo + 4 * (size_t)i + 2) = __floats2half2_rn(l[2], l[3]);
}
__global__ __launch_bounds__(256)
void round_f16_kernel(const float4* __restrict__ src,
                      __half* __restrict__ dst, int n4)
{
    int i = blockIdx.x * blockDim.x + threadIdx.x;
    if (i >= n4) return;
    float4 v = src[i];
    *(__half2*)(dst + 4 * (size_t)i)     = __floats2half2_rn(v.x, v.y);
    *(__half2*)(dst + 4 * (size_t)i + 2) = __floats2half2_rn(v.z, v.w);
}

// ---------------------------------------------------------------------------
// fp16 2-term GEMM on HMMA:  C[M,N] = (Ah+Al)[M,K] * B[N,K]^T, K = 1024.
// 256 threads = 8 warps (2m x 4n), warp tile 64x32, BK=32.
// 3-stage cp.async ring, one barrier per k-chunk.
// mode 0: fp32 store to C.  mode 1: QKV epilogue -> per-head planes
// (Q hi/lo scaled 1/8; K, V single fp16).
// ---------------------------------------------------------------------------
#define BKS      32
#define NKI      (DMODEL / BKS)         // 32
#define PLANE_B  (128 * 80)             // 10240 bytes (64B rows + 16 pad)
#define STAGE_B3 (3 * PLANE_B)          // Ah, Al, B
#define NSTG     3
#define GSMEM    (NSTG * STAGE_B3)      // 92160 bytes

__global__ __launch_bounds__(256, 1)
void gemm_f16_kernel(const __half* __restrict__ Ahi,
                     const __half* __restrict__ Alo,
                     const __half* __restrict__ B,
                     float* __restrict__ C, int N, int mode)
{
    extern __shared__ char smem[];
    const uint32_t sbase = smem_u32(smem);
    const int tid  = threadIdx.x;
    const int wid  = tid >> 5;
    const int lane = tid & 31;
    const int wm   = wid >> 2;          // 0..1  (64-row slab)
    const int wn   = wid & 3;           // 0..3  (32-col slab)
    const int m0   = blockIdx.y * 128;
    const int n0   = blockIdx.x * 128;
    const int K    = DMODEL;

    const __half* gsrc[3] = {
        Ahi + (size_t)m0 * K, Alo + (size_t)m0 * K, B + (size_t)n0 * K };

    // cp.async: per stage 3 planes x 128 rows x 64B; 6 cp16 per thread
    const int r2 = tid >> 1;            // 0..127
    const int c2 = (tid & 1) * 2;       // chunk base 0 or 2
    auto issue_stage = [&](int buf, int kc) {
        const uint32_t dst = sbase + buf * STAGE_B3 + r2 * 80 + c2 * 16;
        const size_t goff = (size_t)r2 * K + kc + c2 * 8;
#pragma unroll
        for (int p = 0; p < 3; ++p) {
            cp16(dst + p * PLANE_B,      gsrc[p] + goff);
            cp16(dst + p * PLANE_B + 16, gsrc[p] + goff + 8);
        }
    };

    issue_stage(0, 0);      CP_COMMIT();
    issue_stage(1, BKS);    CP_COMMIT();

    float acc[4][4][4];
#pragma unroll
    for (int mi = 0; mi < 4; ++mi)
#pragma unroll
        for (int nj = 0; nj < 4; ++nj)
#pragma unroll
            for (int q = 0; q < 4; ++q) acc[mi][nj][q] = 0.0f;

    for (int kt = 0; kt < NKI; ++kt) {
        CP_WAIT1();            // chunk kt landed
        __syncthreads();       // everyone done with buffer being refilled
        if (kt + 2 < NKI) {
            issue_stage((kt + 2) % NSTG, (kt + 2) * BKS);
            CP_COMMIT();
        }

        const uint32_t sb = sbase + (kt % NSTG) * STAGE_B3;
#pragma unroll
        for (int ks = 0; ks < 2; ++ks) {
            uint32_t ah[4][4], al[4][4], b[4][2];
#pragma unroll
            for (int mi = 0; mi < 4; ++mi) {
                const int row = wm * 64 + mi * 16 + (lane & 15);
                const uint32_t a = sb + row * 80 + ks * 32 + (lane >> 4) * 16;
                ldsm_x4(ah[mi][0], ah[mi][1], ah[mi][2], ah[mi][3], a);
                ldsm_x4(al[mi][0], al[mi][1], al[mi][2], al[mi][3], a + PLANE_B);
            }
#pragma unroll
            for (int p2 = 0; p2 < 2; ++p2) {    // nj pair 2p2, 2p2+1
                const int row = wn * 32 + p2 * 16 + (lane & 15);
                const uint32_t a = sb + 2 * PLANE_B + row * 80
                                 + ks * 32 + (lane >> 4) * 16;
                uint32_t r0, r1, r2x, r3;
                ldsm_x4(r0, r1, r2x, r3, a);
                b[2 * p2][0] = r0; b[2 * p2][1] = r2x;
                b[2 * p2 + 1][0] = r1; b[2 * p2 + 1][1] = r3;
            }
#pragma unroll
            for (int mi = 0; mi < 4; ++mi)
#pragma unroll
                for (int nj = 0; nj < 4; ++nj) {
                    mma_f16(acc[mi][nj], ah[mi], b[nj]);
                    mma_f16(acc[mi][nj], al[mi], b[nj]);
                }
        }
    }

#pragma unroll
    for (int mi = 0; mi < 4; ++mi)
#pragma unroll
        for (int nj = 0; nj < 4; ++nj) {
            const int mrow = m0 + wm * 64 + mi * 16 + (lane >> 2);
            const int ncol = n0 + wn * 32 + nj * 8 + (lane & 3) * 2;
            if (mode == 0) {
                *(float2*)(C + (size_t)mrow * N + ncol) =
                    make_float2(acc[mi][nj][0], acc[mi][nj][1]);
                *(float2*)(C + (size_t)(mrow + 8) * N + ncol) =
                    make_float2(acc[mi][nj][2], acc[mi][nj][3]);
            } else {
                const int cc = ncol >> 10;
                const int h  = (ncol >> 6) & (HEADS - 1);
                const int dk = ncol & (DK - 1);
#pragma unroll
                for (int half_ = 0; half_ < 2; ++half_) {
                    const int m = mrow + half_ * 8;
                    const int b_ = m >> 11;
                    const int s  = m & (SEQ - 1);
                    const size_t off =
                        ((size_t)(b_ * HEADS + h) * SEQ + s) * DK + dk;
                    float v0 = acc[mi][nj][half_ * 2];
                    float v1 = acc[mi][nj][half_ * 2 + 1];
                    if (cc == 0) {          // Q: scale + split hi/lo
                        v0 *= 0.125f; v1 *= 0.125f;
                        __half2 hi2;
                        hi2.x = __float2half_rn(v0);
                        hi2.y = __float2half_rn(v1);
                        *(__half2*)(g_qh + off) = hi2;
                        *(__half2*)(g_ql + off) = __floats2half2_rn(
                            v0 - __half2float(hi2.x), v1 - __half2float(hi2.y));
                    } else if (cc == 1) {   // K: single fp16
                        *(__half2*)(g_ks + off) = __floats2half2_rn(v0, v1);
                    } else {                // V: single fp16
                        *(__half2*)(g_vs + off) = __floats2half2_rn(v0, v1);
                    }
                }
            }
        }
}

// ---------------------------------------------------------------------------
// Causal flash attention on HMMA, fp16 2-term.
// S = (Qh+Ql)·K^T  (K single fp16);  O += (Ph+Pl)·V  (V single fp16).
// Grid: (SEQ/128, BH). Block: 256 threads = 8 warps; warp owns 16 q-rows.
// KV tiles of 64 keys; next tile register-prefetched during compute.
// ---------------------------------------------------------------------------
#define ASTR   144                    // 64 fp16 = 128B data + 16 pad
#define A_QH   0
#define A_QL   (128 * ASTR)
#define A_K    (2 * 128 * ASTR)
#define A_V    (A_K + 64 * ASTR)
#define A_TOTAL (A_V + 64 * ASTR)     // 55296 bytes

__global__ __launch_bounds__(256, 1)
void attn_f16_kernel()
{
    extern __shared__ char smem[];
    const uint32_t sb = smem_u32(smem);
    const int tid  = threadIdx.x;
    const int w    = tid >> 5;
    const int lane = tid & 31;
    const int qt   = blockIdx.x;          // 128-row q tile
    const int bh   = blockIdx.y;
    const int q0   = qt * 128;

    const __half* Qh = g_qh + ((size_t)bh * SEQ + q0) * DK;
    const __half* Ql = g_ql + ((size_t)bh * SEQ + q0) * DK;
    const __half* Ks = g_ks + (size_t)bh * SEQ * DK;
    const __half* Vs = g_vs + (size_t)bh * SEQ * DK;

    const int r_ = tid >> 3;              // 0..31
    const int c_ = tid & 7;               // 16B chunk

    // Load Q tile (128 x 64) hi/lo + KV tile 0 into smem
#pragma unroll
    for (int t = 0; t < 4; ++t) {
        const int row = r_ + t * 32;
        *(uint4*)(smem + A_QH + row * ASTR + c_ * 16) =
            *(const uint4*)(Qh + (size_t)row * DK + c_ * 8);
        *(uint4*)(smem + A_QL + row * ASTR + c_ * 16) =
            *(const uint4*)(Ql + (size_t)row * DK + c_ * 8);
    }
#pragma unroll
    for (int t = 0; t < 2; ++t) {
        const int row = r_ + t * 32;
        const size_t g = (size_t)row * DK + c_ * 8;
        const int so = row * ASTR + c_ * 16;
        *(uint4*)(smem + A_K + so) = *(const uint4*)(Ks + g);
        *(uint4*)(smem + A_V + so) = *(const uint4*)(Vs + g);
    }
    __syncthreads();

    // Q fragments (registers, whole kernel)
    uint32_t qfh[4][4], qfl[4][4];
#pragma unroll
    for (int kk = 0; kk < 4; ++kk) {
        const int row = w * 16 + (lane & 15);
        const uint32_t a = sb + A_QH + row * ASTR + kk * 32 + (lane >> 4) * 16;
        ldsm_x4(qfh[kk][0], qfh[kk][1], qfh[kk][2], qfh[kk][3], a);
        ldsm_x4(qfl[kk][0], qfl[kk][1], qfl[kk][2], qfl[kk][3],
                a + (A_QL - A_QH));
    }

    float o[8][4];
#pragma unroll
    for (int nj = 0; nj < 8; ++nj)
#pragma unroll
        for (int q = 0; q < 4; ++q) o[nj][q] = 0.0f;
    float mA = -1e30f, mB = -1e30f, lA = 0.0f, lB = 0.0f;

    const int nkt = 2 * qt + 2;
    for (int kt = 0; kt < nkt; ++kt) {
        // Prefetch next KV tile into registers
        uint4 pf[4];
        const bool havepf = (kt + 1 < nkt);
        if (havepf) {
#pragma unroll
            for (int t = 0; t < 2; ++t) {
                const int row = r_ + t * 32;
                const size_t g = (size_t)((kt + 1) * 64 + row) * DK + c_ * 8;
                pf[t * 2 + 0] = *(const uint4*)(Ks + g);
                pf[t * 2 + 1] = *(const uint4*)(Vs + g);
            }
        }

        // Warps 0-3 fully masked on the last diagonal tile
        if (!(kt == 2 * qt + 1 && w < 4)) {
            // ---- S = Q K^T (2 terms) ----
            float s[8][4];
#pragma unroll
            for (int nj = 0; nj < 8; ++nj)
#pragma unroll
                for (int q = 0; q < 4; ++q) s[nj][q] = 0.0f;

#pragma unroll
            for (int kk = 0; kk < 4; ++kk) {
                uint32_t bk[8][2];
#pragma unroll
                for (int p2 = 0; p2 < 4; ++p2) {
                    const uint32_t a = sb + A_K + (p2 * 16 + (lane & 15)) * ASTR
                                     + kk * 32 + (lane >> 4) * 16;
                    uint32_t r0, r1, r2, r3;
                    ldsm_x4(r0, r1, r2, r3, a);
                    bk[2 * p2][0] = r0; bk[2 * p2][1] = r2;
                    bk[2 * p2 + 1][0] = r1; bk[2 * p2 + 1][1] = r3;
                }
#pragma unroll
                for (int nj = 0; nj < 8; ++nj) {
                    mma_f16(s[nj], qfh[kk], bk[nj]);
                    mma_f16(s[nj], qfl[kk], bk[nj]);
                }
            }

            // ---- causal mask (diagonal tiles only) ----
            if (kt >= 2 * qt) {
                const int rowA = q0 + w * 16 + (lane >> 2);
                const int k0   = kt * 64;
#pragma unroll
                for (int nj = 0; nj < 8; ++nj) {
                    const int c0 = k0 + nj * 8 + (lane & 3) * 2;
                    if (c0 > rowA)     s[nj][0] = -1e30f;
                    if (c0 + 1 > rowA) s[nj][1] = -1e30f;
                    if (c0 > rowA + 8)     s[nj][2] = -1e30f;
                    if (c0 + 1 > rowA + 8) s[nj][3] = -1e30f;
                }
            }

            // ---- online softmax ----
            float tmA = -1e30f, tmB = -1e30f;
#pragma unroll
            for (int nj = 0; nj < 8; ++nj) {
                tmA = fmaxf(tmA, fmaxf(s[nj][0], s[nj][1]));
                tmB = fmaxf(tmB, fmaxf(s[nj][2], s[nj][3]));
            }
            tmA = fmaxf(tmA, __shfl_xor_sync(0xffffffffu, tmA, 1));
            tmA = fmaxf(tmA, __shfl_xor_sync(0xffffffffu, tmA, 2));
            tmB = fmaxf(tmB, __shfl_xor_sync(0xffffffffu, tmB, 1));
            tmB = fmaxf(tmB, __shfl_xor_sync(0xffffffffu, tmB, 2));
            const float mnA = fmaxf(mA, tmA);
            const float mnB = fmaxf(mB, tmB);
            const float fA = __expf(mA - mnA);
            const float fB = __expf(mB - mnB);
            mA = mnA; mB = mnB;

            float rsA = 0.0f, rsB = 0.0f;
#pragma unroll
            for (int nj = 0; nj < 8; ++nj) {
                s[nj][0] = __expf(s[nj][0] - mnA);
                s[nj][1] = __expf(s[nj][1] - mnA);
                s[nj][2] = __expf(s[nj][2] - mnB);
                s[nj][3] = __expf(s[nj][3] - mnB);
                rsA += s[nj][0] + s[nj][1];
                rsB += s[nj][2] + s[nj][3];
            }
            rsA += __shfl_xor_sync(0xffffffffu, rsA, 1);
            rsA += __shfl_xor_sync(0xffffffffu, rsA, 2);
            rsB += __shfl_xor_sync(0xffffffffu, rsB, 1);
            rsB += __shfl_xor_sync(0xffffffffu, rsB, 2);
            lA = lA * fA + rsA;
            lB = lB * fB + rsB;
#pragma unroll
            for (int nj = 0; nj < 8; ++nj) {
                o[nj][0] *= fA; o[nj][1] *= fA;
                o[nj][2] *= fB; o[nj][3] *= fB;
            }

            // ---- O += P V (2 terms; P split exactly into fp16 hi+lo) ----
#pragma unroll
            for (int kk = 0; kk < 4; ++kk) {
                const int j0 = 2 * kk, j1 = 2 * kk + 1;
                uint32_t ph[4], pl[4];
                ph[0] = pack_f16(s[j0][0], s[j0][1]);
                ph[1] = pack_f16(s[j0][2], s[j0][3]);
                ph[2] = pack_f16(s[j1][0], s[j1][1]);
                ph[3] = pack_f16(s[j1][2], s[j1][3]);
#pragma unroll
                for (int q = 0; q < 4; ++q) {
                    const float* sv = (q < 2) ? s[j0] : s[j1];
                    __half2* hp = (__half2*)&ph[q];
                    pl[q] = pack_f16(sv[(q & 1) * 2]     - __half2float(hp->x),
                                     sv[(q & 1) * 2 + 1] - __half2float(hp->y));
                }
#pragma unroll
                for (int p2 = 0; p2 < 4; ++p2) {
                    const uint32_t a = sb + A_V
                        + (kk * 16 + (lane & 7) + ((lane >> 3) & 1) * 8) * ASTR
                        + p2 * 32 + (lane >> 4) * 16;
                    uint32_t r0, r1, r2, r3;
                    ldsm_x4t(r0, r1, r2, r3, a);
                    uint32_t bv0[2] = {r0, r1}, bv1[2] = {r2, r3};
                    mma_f16(o[2 * p2],     ph, bv0);
                    mma_f16(o[2 * p2],     pl, bv0);
                    mma_f16(o[2 * p2 + 1], ph, bv1);
                    mma_f16(o[2 * p2 + 1], pl, bv1);
                }
            }
        }

        if (havepf) {
            __syncthreads();
#pragma unroll
            for (int t = 0; t < 2; ++t) {
                const int row = r_ + t * 32;
                const int so = row * ASTR + c_ * 16;
                *(uint4*)(smem + A_K + so) = pf[t * 2 + 0];
                *(uint4*)(smem + A_V + so) = pf[t * 2 + 1];
            }
            __syncthreads();
        }
    }

    // ---- normalize + split-store heads [b*S+s][h*DK+dk] as fp16 hi/lo ----
    const int b = bh >> 4;
    const int h = bh & 15;
    const float iA = 1.0f / lA;
    const float iB = 1.0f / lB;
    const int rowA = q0 + w * 16 + (lane >> 2);
#pragma unroll
    for (int nj = 0; nj < 8; ++nj) {
        const int col = h * DK + nj * 8 + (lane & 3) * 2;
        float v0 = o[nj][0] * iA, v1 = o[nj][1] * iA;
        float v2 = o[nj][2] * iB, v3 = o[nj][3] * iB;
        size_t off = (size_t)(b * SEQ + rowA) * DMODEL + col;
        __half2 hi2;
        hi2.x = __float2half_rn(v0);
        hi2.y = __float2half_rn(v1);
        *(__half2*)(g_hhi + off) = hi2;
        *(__half2*)(g_hlo + off) = __floats2half2_rn(
            v0 - __half2float(hi2.x), v1 - __half2float(hi2.y));
        off += 8 * DMODEL;
        hi2.x = __float2half_rn(v2);
        hi2.y = __float2half_rn(v3);
        *(__half2*)(g_hhi + off) = hi2;
        *(__half2*)(g_hlo + off) = __floats2half2_rn(
            v2 - __half2float(hi2.x), v3 - __half2float(hi2.y));
    }
}

// ---------------------------------------------------------------------------
extern "C" void kernel_launch(void* const* d_in, const int* in_sizes, int n_in,
                              void* d_out, int out_size)
{
    const float* x     = (const float*)d_in[0];
    const float* w_qkv = (const float*)d_in[1];
    const float* w_o   = (const float*)d_in[2];
    float* out = (float*)d_out;

    __half *xhi, *xlo, *wq, *wo, *hhi, *hlo;
    cudaGetSymbolAddress((void**)&xhi, g_xhi);
    cudaGetSymbolAddress((void**)&xlo, g_xlo);
    cudaGetSymbolAddress((void**)&wq,  g_wq);
    cudaGetSymbolAddress((void**)&wo,  g_wo);
    cudaGetSymbolAddress((void**)&hhi, g_hhi);
    cudaGetSymbolAddress((void**)&hlo, g_hlo);

    cudaFuncSetAttribute(gemm_f16_kernel,
                         cudaFuncAttributeMaxDynamicSharedMemorySize, GSMEM);
    cudaFuncSetAttribute(attn_f16_kernel,
                         cudaFuncAttributeMaxDynamicSharedMemorySize, A_TOTAL);

    // 1) convert inputs: x -> fp16 hi/lo, weights -> fp16 single
    split_f16_kernel<<<NTOK * DMODEL / 4 / 256, 256>>>((const float4*)x, xhi, xlo,
                                                       NTOK * DMODEL / 4);
    round_f16_kernel<<<3 * DMODEL * DMODEL / 4 / 256, 256>>>((const float4*)w_qkv,
                                                             wq, 3 * DMODEL * DMODEL / 4);
    round_f16_kernel<<<DMODEL * DMODEL / 4 / 256, 256>>>((const float4*)w_o,
                                                         wo, DMODEL * DMODEL / 4);

    // 2) QKV projection -> per-head planes (Q hi/lo scaled, K/V single)
    gemm_f16_kernel<<<dim3(24, 64), 256, GSMEM>>>(xhi, xlo, wq,
                                                  nullptr, 3 * DMODEL, 1);
    // 3) causal flash attention (fp16 2-term) -> heads hi/lo
    attn_f16_kernel<<<dim3(SEQ / 128, BH), 256, A_TOTAL>>>();

    // 4) output projection
    gemm_f16_kernel<<<dim3(8, 64), 256, GSMEM>>>(hhi, hlo, wo,
                                                 out, DMODEL, 0);
}

// round 10
// speedup vs baseline: 1.7542x; 1.2583x over previous
#include <cuda_runtime.h>
#include <cuda_fp16.h>
#include <stdint.h>

// Problem constants
#define BATCH   4
#define HEADS   16
#define SEQ     2048
#define DK      64
#define DMODEL  1024
#define NTOK    (BATCH * SEQ)            // 8192
#define BH      (BATCH * HEADS)          // 64

// Scratch (device globals: cudaMalloc is forbidden)
__device__ __half g_xhi[NTOK * DMODEL];
__device__ __half g_xlo[NTOK * DMODEL];
__device__ __half g_wq [3 * DMODEL * DMODEL];
__device__ __half g_wo [DMODEL * DMODEL];
__device__ __half g_qh [BH * SEQ * DK];          // Q hi (pre-scaled 1/8)
__device__ __half g_ql [BH * SEQ * DK];          // Q lo
__device__ __half g_ks [BH * SEQ * DK];          // K single fp16
__device__ __half g_vs [BH * SEQ * DK];          // V single fp16
__device__ __half g_hs [NTOK * DMODEL];          // heads single fp16

// ---------------------------------------------------------------------------
// Warp MMA + async-copy helpers (sm_80+ instructions only)
// ---------------------------------------------------------------------------
__device__ __forceinline__ uint32_t smem_u32(const void* p) {
    uint32_t a;
    asm("{ .reg .u64 t; cvta.to.shared.u64 t, %1; cvt.u32.u64 %0, t; }"
        : "=r"(a) : "l"(p));
    return a;
}
__device__ __forceinline__ void ldsm_x4(uint32_t& r0, uint32_t& r1,
                                        uint32_t& r2, uint32_t& r3, uint32_t addr) {
    asm volatile("ldmatrix.sync.aligned.m8n8.x4.shared.b16 {%0,%1,%2,%3}, [%4];"
                 : "=r"(r0), "=r"(r1), "=r"(r2), "=r"(r3) : "r"(addr));
}
__device__ __forceinline__ void ldsm_x4t(uint32_t& r0, uint32_t& r1,
                                         uint32_t& r2, uint32_t& r3, uint32_t addr) {
    asm volatile("ldmatrix.sync.aligned.m8n8.x4.trans.shared.b16 {%0,%1,%2,%3}, [%4];"
                 : "=r"(r0), "=r"(r1), "=r"(r2), "=r"(r3) : "r"(addr));
}
__device__ __forceinline__ void mma_f16(float* c, const uint32_t* a, const uint32_t* b) {
    asm volatile("mma.sync.aligned.m16n8k16.row.col.f32.f16.f16.f32 "
                 "{%0,%1,%2,%3}, {%4,%5,%6,%7}, {%8,%9}, {%0,%1,%2,%3};"
                 : "+f"(c[0]), "+f"(c[1]), "+f"(c[2]), "+f"(c[3])
                 : "r"(a[0]), "r"(a[1]), "r"(a[2]), "r"(a[3]),
                   "r"(b[0]), "r"(b[1]));
}
__device__ __forceinline__ uint32_t pack_f16(float a, float b) {
    __half2 h = __floats2half2_rn(a, b);
    return *(uint32_t*)&h;
}
__device__ __forceinline__ void cp16(uint32_t s, const void* g) {
    asm volatile("cp.async.cg.shared.global [%0], [%1], 16;" :: "r"(s), "l"(g));
}
#define CP_COMMIT() asm volatile("cp.async.commit_group;")
#define CP_WAIT1()  asm volatile("cp.async.wait_group 1;")

// ---------------------------------------------------------------------------
// fp32 -> fp16 hi/lo split, and fp32 -> fp16 round
// ---------------------------------------------------------------------------
__global__ __launch_bounds__(256)
void split_f16_kernel(const float4* __restrict__ src,
                      __half* __restrict__ hi, __half* __restrict__ lo, int n4)
{
    int i = blockIdx.x * blockDim.x + threadIdx.x;
    if (i >= n4) return;
    float4 v = src[i];
    float f[4] = {v.x, v.y, v.z, v.w};
    __half h[4];
    float  l[4];
#pragma unroll
    for (int j = 0; j < 4; ++j) {
        h[j] = __float2half_rn(f[j]);
        l[j] = f[j] - __half2float(h[j]);
    }
    __half2 h01; h01.x = h[0]; h01.y = h[1];
    __half2 h23; h23.x = h[2]; h23.y = h[3];
    *(__half2*)(hi + 4 * (size_t)i)     = h01;
    *(__half2*)(hi + 4 * (size_t)i + 2) = h23;
    *(__half2*)(lo + 4 * (size_t)i)     = __floats2half2_rn(l[0], l[1]);
    *(__half2*)(lo + 4 * (size_t)i + 2) = __floats2half2_rn(l[2], l[3]);
}
__global__ __launch_bounds__(256)
void round_f16_kernel(const float4* __restrict__ src,
                      __half* __restrict__ dst, int n4)
{
    int i = blockIdx.x * blockDim.x + threadIdx.x;
    if (i >= n4) return;
    float4 v = src[i];
    *(__half2*)(dst + 4 * (size_t)i)     = __floats2half2_rn(v.x, v.y);
    *(__half2*)(dst + 4 * (size_t)i + 2) = __floats2half2_rn(v.z, v.w);
}

// ---------------------------------------------------------------------------
// fp16 GEMM on HMMA:  C[M,N] = (Ah[+Al])[M,K] * B[N,K]^T, K = 1024.
// 256 threads = 8 warps (2m x 4n), warp tile 64x32, BK=32.
// 3-stage cp.async ring, one barrier per k-chunk.
// A-lo term used iff (mode==1 && n0<1024 [Q columns]) or (mode==0 && Alo!=0).
// mode 0: fp32 store to C.  mode 1: QKV epilogue -> per-head planes
// (Q hi/lo scaled 1/8; K, V single fp16).
// ---------------------------------------------------------------------------
#define BKS      32
#define NKI      (DMODEL / BKS)         // 32
#define PLANE_B  (128 * 80)             // 10240 bytes (64B rows + 16 pad)
#define STAGE_B3 (3 * PLANE_B)          // Ah, Al, B
#define NSTG     3
#define GSMEM    (NSTG * STAGE_B3)      // 92160 bytes

__global__ __launch_bounds__(256, 1)
void gemm_f16_kernel(const __half* __restrict__ Ahi,
                     const __half* __restrict__ Alo,
                     const __half* __restrict__ B,
                     float* __restrict__ C, int N, int mode)
{
    extern __shared__ char smem[];
    const uint32_t sbase = smem_u32(smem);
    const int tid  = threadIdx.x;
    const int wid  = tid >> 5;
    const int lane = tid & 31;
    const int wm   = wid >> 2;          // 0..1  (64-row slab)
    const int wn   = wid & 3;           // 0..3  (32-col slab)
    const int m0   = blockIdx.y * 128;
    const int n0   = blockIdx.x * 128;
    const int K    = DMODEL;

    const bool use_al = (mode == 1) ? (n0 < DMODEL) : (Alo != nullptr);

    const __half* gA  = Ahi + (size_t)m0 * K;
    const __half* gAl = use_al ? (Alo + (size_t)m0 * K) : gA;
    const __half* gB  = B   + (size_t)n0 * K;

    // cp.async: per stage {Ah, [Al], B} planes x 128 rows x 64B
    const int r2 = tid >> 1;            // 0..127
    const int c2 = (tid & 1) * 2;       // chunk base 0 or 2
    auto issue_stage = [&](int buf, int kc) {
        const uint32_t dst = sbase + buf * STAGE_B3 + r2 * 80 + c2 * 16;
        const size_t goff = (size_t)r2 * K + kc + c2 * 8;
        cp16(dst,                    gA + goff);
        cp16(dst + 16,               gA + goff + 8);
        if (use_al) {
            cp16(dst + PLANE_B,      gAl + goff);
            cp16(dst + PLANE_B + 16, gAl + goff + 8);
        }
        cp16(dst + 2 * PLANE_B,      gB + goff);
        cp16(dst + 2 * PLANE_B + 16, gB + goff + 8);
    };

    issue_stage(0, 0);      CP_COMMIT();
    issue_stage(1, BKS);    CP_COMMIT();

    float acc[4][4][4];
#pragma unroll
    for (int mi = 0; mi < 4; ++mi)
#pragma unroll
        for (int nj = 0; nj < 4; ++nj)
#pragma unroll
            for (int q = 0; q < 4; ++q) acc[mi][nj][q] = 0.0f;

    for (int kt = 0; kt < NKI; ++kt) {
        CP_WAIT1();            // chunk kt landed
        __syncthreads();       // everyone done with buffer being refilled
        if (kt + 2 < NKI) {
            issue_stage((kt + 2) % NSTG, (kt + 2) * BKS);
            CP_COMMIT();
        }

        const uint32_t sb = sbase + (kt % NSTG) * STAGE_B3;
#pragma unroll
        for (int ks = 0; ks < 2; ++ks) {
            uint32_t ah[4][4], al[4][4], b[4][2];
#pragma unroll
            for (int mi = 0; mi < 4; ++mi) {
                const int row = wm * 64 + mi * 16 + (lane & 15);
                const uint32_t a = sb + row * 80 + ks * 32 + (lane >> 4) * 16;
                ldsm_x4(ah[mi][0], ah[mi][1], ah[mi][2], ah[mi][3], a);
                if (use_al)
                    ldsm_x4(al[mi][0], al[mi][1], al[mi][2], al[mi][3], a + PLANE_B);
            }
#pragma unroll
            for (int p2 = 0; p2 < 2; ++p2) {    // nj pair 2p2, 2p2+1
                const int row = wn * 32 + p2 * 16 + (lane & 15);
                const uint32_t a = sb + 2 * PLANE_B + row * 80
                                 + ks * 32 + (lane >> 4) * 16;
                uint32_t r0, r1, r2x, r3;
                ldsm_x4(r0, r1, r2x, r3, a);
                b[2 * p2][0] = r0; b[2 * p2][1] = r2x;
                b[2 * p2 + 1][0] = r1; b[2 * p2 + 1][1] = r3;
            }
#pragma unroll
            for (int mi = 0; mi < 4; ++mi)
#pragma unroll
                for (int nj = 0; nj < 4; ++nj) {
                    mma_f16(acc[mi][nj], ah[mi], b[nj]);
                    if (use_al) mma_f16(acc[mi][nj], al[mi], b[nj]);
                }
        }
    }

#pragma unroll
    for (int mi = 0; mi < 4; ++mi)
#pragma unroll
        for (int nj = 0; nj < 4; ++nj) {
            const int mrow = m0 + wm * 64 + mi * 16 + (lane >> 2);
            const int ncol = n0 + wn * 32 + nj * 8 + (lane & 3) * 2;
            if (mode == 0) {
                *(float2*)(C + (size_t)mrow * N + ncol) =
                    make_float2(acc[mi][nj][0], acc[mi][nj][1]);
                *(float2*)(C + (size_t)(mrow + 8) * N + ncol) =
                    make_float2(acc[mi][nj][2], acc[mi][nj][3]);
            } else {
                const int cc = ncol >> 10;
                const int h  = (ncol >> 6) & (HEADS - 1);
                const int dk = ncol & (DK - 1);
#pragma unroll
                for (int half_ = 0; half_ < 2; ++half_) {
                    const int m = mrow + half_ * 8;
                    const int b_ = m >> 11;
                    const int s  = m & (SEQ - 1);
                    const size_t off =
                        ((size_t)(b_ * HEADS + h) * SEQ + s) * DK + dk;
                    float v0 = acc[mi][nj][half_ * 2];
                    float v1 = acc[mi][nj][half_ * 2 + 1];
                    if (cc == 0) {          // Q: scale + split hi/lo
                        v0 *= 0.125f; v1 *= 0.125f;
                        __half2 hi2;
                        hi2.x = __float2half_rn(v0);
                        hi2.y = __float2half_rn(v1);
                        *(__half2*)(g_qh + off) = hi2;
                        *(__half2*)(g_ql + off) = __floats2half2_rn(
                            v0 - __half2float(hi2.x), v1 - __half2float(hi2.y));
                    } else if (cc == 1) {   // K: single fp16
                        *(__half2*)(g_ks + off) = __floats2half2_rn(v0, v1);
                    } else {                // V: single fp16
                        *(__half2*)(g_vs + off) = __floats2half2_rn(v0, v1);
                    }
                }
            }
        }
}

// ---------------------------------------------------------------------------
// Causal flash attention on HMMA, fp16.
// S = (Qh+Ql)·K^T (2 terms);  O += P·V (1 term, P rounded to fp16).
// Grid: (SEQ/128, BH). Block: 256 threads = 8 warps; warp owns 16 q-rows.
// KV tiles of 64 keys; next tile register-prefetched during compute.
// ---------------------------------------------------------------------------
#define ASTR   144                    // 64 fp16 = 128B data + 16 pad
#define A_QH   0
#define A_QL   (128 * ASTR)
#define A_K    (2 * 128 * ASTR)
#define A_V    (A_K + 64 * ASTR)
#define A_TOTAL (A_V + 64 * ASTR)     // 55296 bytes

__global__ __launch_bounds__(256, 1)
void attn_f16_kernel()
{
    extern __shared__ char smem[];
    const uint32_t sb = smem_u32(smem);
    const int tid  = threadIdx.x;
    const int w    = tid >> 5;
    const int lane = tid & 31;
    const int qt   = blockIdx.x;          // 128-row q tile
    const int bh   = blockIdx.y;
    const int q0   = qt * 128;

    const __half* Qh = g_qh + ((size_t)bh * SEQ + q0) * DK;
    const __half* Ql = g_ql + ((size_t)bh * SEQ + q0) * DK;
    const __half* Ks = g_ks + (size_t)bh * SEQ * DK;
    const __half* Vs = g_vs + (size_t)bh * SEQ * DK;

    const int r_ = tid >> 3;              // 0..31
    const int c_ = tid & 7;               // 16B chunk

    // Load Q tile (128 x 64) hi/lo + KV tile 0 into smem
#pragma unroll
    for (int t = 0; t < 4; ++t) {
        const int row = r_ + t * 32;
        *(uint4*)(smem + A_QH + row * ASTR + c_ * 16) =
            *(const uint4*)(Qh + (size_t)row * DK + c_ * 8);
        *(uint4*)(smem + A_QL + row * ASTR + c_ * 16) =
            *(const uint4*)(Ql + (size_t)row * DK + c_ * 8);
    }
#pragma unroll
    for (int t = 0; t < 2; ++t) {
        const int row = r_ + t * 32;
        const size_t g = (size_t)row * DK + c_ * 8;
        const int so = row * ASTR + c_ * 16;
        *(uint4*)(smem + A_K + so) = *(const uint4*)(Ks + g);
        *(uint4*)(smem + A_V + so) = *(const uint4*)(Vs + g);
    }
    __syncthreads();

    // Q fragments (registers, whole kernel)
    uint32_t qfh[4][4], qfl[4][4];
#pragma unroll
    for (int kk = 0; kk < 4; ++kk) {
        const int row = w * 16 + (lane & 15);
        const uint32_t a = sb + A_QH + row * ASTR + kk * 32 + (lane >> 4) * 16;
        ldsm_x4(qfh[kk][0], qfh[kk][1], qfh[kk][2], qfh[kk][3], a);
        ldsm_x4(qfl[kk][0], qfl[kk][1], qfl[kk][2], qfl[kk][3],
                a + (A_QL - A_QH));
    }

    float o[8][4];
#pragma unroll
    for (int nj = 0; nj < 8; ++nj)
#pragma unroll
        for (int q = 0; q < 4; ++q) o[nj][q] = 0.0f;
    float mA = -1e30f, mB = -1e30f, lA = 0.0f, lB = 0.0f;

    const int nkt = 2 * qt + 2;
    for (int kt = 0; kt < nkt; ++kt) {
        // Prefetch next KV tile into registers
        uint4 pf[4];
        const bool havepf = (kt + 1 < nkt);
        if (havepf) {
#pragma unroll
            for (int t = 0; t < 2; ++t) {
                const int row = r_ + t * 32;
                const size_t g = (size_t)((kt + 1) * 64 + row) * DK + c_ * 8;
                pf[t * 2 + 0] = *(const uint4*)(Ks + g);
                pf[t * 2 + 1] = *(const uint4*)(Vs + g);
            }
        }

        // Warps 0-3 fully masked on the last diagonal tile
        if (!(kt == 2 * qt + 1 && w < 4)) {
            // ---- S = Q K^T (2 terms) ----
            float s[8][4];
#pragma unroll
            for (int nj = 0; nj < 8; ++nj)
#pragma unroll
                for (int q = 0; q < 4; ++q) s[nj][q] = 0.0f;

#pragma unroll
            for (int kk = 0; kk < 4; ++kk) {
                uint32_t bk[8][2];
#pragma unroll
                for (int p2 = 0; p2 < 4; ++p2) {
                    const uint32_t a = sb + A_K + (p2 * 16 + (lane & 15)) * ASTR
                                     + kk * 32 + (lane >> 4) * 16;
                    uint32_t r0, r1, r2, r3;
                    ldsm_x4(r0, r1, r2, r3, a);
                    bk[2 * p2][0] = r0; bk[2 * p2][1] = r2;
                    bk[2 * p2 + 1][0] = r1; bk[2 * p2 + 1][1] = r3;
                }
#pragma unroll
                for (int nj = 0; nj < 8; ++nj) {
                    mma_f16(s[nj], qfh[kk], bk[nj]);
                    mma_f16(s[nj], qfl[kk], bk[nj]);
                }
            }

            // ---- causal mask (diagonal tiles only) ----
            if (kt >= 2 * qt) {
                const int rowA = q0 + w * 16 + (lane >> 2);
                const int k0   = kt * 64;
#pragma unroll
                for (int nj = 0; nj < 8; ++nj) {
                    const int c0 = k0 + nj * 8 + (lane & 3) * 2;
                    if (c0 > rowA)     s[nj][0] = -1e30f;
                    if (c0 + 1 > rowA) s[nj][1] = -1e30f;
                    if (c0 > rowA + 8)     s[nj][2] = -1e30f;
                    if (c0 + 1 > rowA + 8) s[nj][3] = -1e30f;
                }
            }

            // ---- online softmax ----
            float tmA = -1e30f, tmB = -1e30f;
#pragma unroll
            for (int nj = 0; nj < 8; ++nj) {
                tmA = fmaxf(tmA, fmaxf(s[nj][0], s[nj][1]));
                tmB = fmaxf(tmB, fmaxf(s[nj][2], s[nj][3]));
            }
            tmA = fmaxf(tmA, __shfl_xor_sync(0xffffffffu, tmA, 1));
            tmA = fmaxf(tmA, __shfl_xor_sync(0xffffffffu, tmA, 2));
            tmB = fmaxf(tmB, __shfl_xor_sync(0xffffffffu, tmB, 1));
            tmB = fmaxf(tmB, __shfl_xor_sync(0xffffffffu, tmB, 2));
            const float mnA = fmaxf(mA, tmA);
            const float mnB = fmaxf(mB, tmB);
            const float fA = __expf(mA - mnA);
            const float fB = __expf(mB - mnB);
            mA = mnA; mB = mnB;

            float rsA = 0.0f, rsB = 0.0f;
#pragma unroll
            for (int nj = 0; nj < 8; ++nj) {
                s[nj][0] = __expf(s[nj][0] - mnA);
                s[nj][1] = __expf(s[nj][1] - mnA);
                s[nj][2] = __expf(s[nj][2] - mnB);
                s[nj][3] = __expf(s[nj][3] - mnB);
                rsA += s[nj][0] + s[nj][1];
                rsB += s[nj][2] + s[nj][3];
            }
            rsA += __shfl_xor_sync(0xffffffffu, rsA, 1);
            rsA += __shfl_xor_sync(0xffffffffu, rsA, 2);
            rsB += __shfl_xor_sync(0xffffffffu, rsB, 1);
            rsB += __shfl_xor_sync(0xffffffffu, rsB, 2);
            lA = lA * fA + rsA;
            lB = lB * fB + rsB;
#pragma unroll
            for (int nj = 0; nj < 8; ++nj) {
                o[nj][0] *= fA; o[nj][1] *= fA;
                o[nj][2] *= fB; o[nj][3] *= fB;
            }

            // ---- O += P V (1 term; P rounded to fp16) ----
#pragma unroll
            for (int kk = 0; kk < 4; ++kk) {
                const int j0 = 2 * kk, j1 = 2 * kk + 1;
                uint32_t ph[4];
                ph[0] = pack_f16(s[j0][0], s[j0][1]);
                ph[1] = pack_f16(s[j0][2], s[j0][3]);
                ph[2] = pack_f16(s[j1][0], s[j1][1]);
                ph[3] = pack_f16(s[j1][2], s[j1][3]);
#pragma unroll
                for (int p2 = 0; p2 < 4; ++p2) {
                    const uint32_t a = sb + A_V
                        + (kk * 16 + (lane & 7) + ((lane >> 3) & 1) * 8) * ASTR
                        + p2 * 32 + (lane >> 4) * 16;
                    uint32_t r0, r1, r2, r3;
                    ldsm_x4t(r0, r1, r2, r3, a);
                    uint32_t bv0[2] = {r0, r1}, bv1[2] = {r2, r3};
                    mma_f16(o[2 * p2],     ph, bv0);
                    mma_f16(o[2 * p2 + 1], ph, bv1);
                }
            }
        }

        if (havepf) {
            __syncthreads();
#pragma unroll
            for (int t = 0; t < 2; ++t) {
                const int row = r_ + t * 32;
                const int so = row * ASTR + c_ * 16;
                *(uint4*)(smem + A_K + so) = pf[t * 2 + 0];
                *(uint4*)(smem + A_V + so) = pf[t * 2 + 1];
            }
            __syncthreads();
        }
    }

    // ---- normalize + store heads [b*S+s][h*DK+dk] as single fp16 ----
    const int b = bh >> 4;
    const int h = bh & 15;
    const float iA = 1.0f / lA;
    const float iB = 1.0f / lB;
    const int rowA = q0 + w * 16 + (lane >> 2);
#pragma unroll
    for (int nj = 0; nj < 8; ++nj) {
        const int col = h * DK + nj * 8 + (lane & 3) * 2;
        size_t off = (size_t)(b * SEQ + rowA) * DMODEL + col;
        *(__half2*)(g_hs + off) =
            __floats2half2_rn(o[nj][0] * iA, o[nj][1] * iA);
        *(__half2*)(g_hs + off + 8 * DMODEL) =
            __floats2half2_rn(o[nj][2] * iB, o[nj][3] * iB);
    }
}

// ---------------------------------------------------------------------------
extern "C" void kernel_launch(void* const* d_in, const int* in_sizes, int n_in,
                              void* d_out, int out_size)
{
    const float* x     = (const float*)d_in[0];
    const float* w_qkv = (const float*)d_in[1];
    const float* w_o   = (const float*)d_in[2];
    float* out = (float*)d_out;

    __half *xhi, *xlo, *wq, *wo, *hs;
    cudaGetSymbolAddress((void**)&xhi, g_xhi);
    cudaGetSymbolAddress((void**)&xlo, g_xlo);
    cudaGetSymbolAddress((void**)&wq,  g_wq);
    cudaGetSymbolAddress((void**)&wo,  g_wo);
    cudaGetSymbolAddress((void**)&hs,  g_hs);

    cudaFuncSetAttribute(gemm_f16_kernel,
                         cudaFuncAttributeMaxDynamicSharedMemorySize, GSMEM);
    cudaFuncSetAttribute(attn_f16_kernel,
                         cudaFuncAttributeMaxDynamicSharedMemorySize, A_TOTAL);

    // 1) convert inputs: x -> fp16 hi/lo, weights -> fp16 single
    split_f16_kernel<<<NTOK * DMODEL / 4 / 256, 256>>>((const float4*)x, xhi, xlo,
                                                       NTOK * DMODEL / 4);
    round_f16_kernel<<<3 * DMODEL * DMODEL / 4 / 256, 256>>>((const float4*)w_qkv,
                                                             wq, 3 * DMODEL * DMODEL / 4);
    round_f16_kernel<<<DMODEL * DMODEL / 4 / 256, 256>>>((const float4*)w_o,
                                                         wo, DMODEL * DMODEL / 4);

    // 2) QKV projection -> per-head planes
    //    (Q cols: 2-term, split-stored; K/V cols: 1-term, single fp16)
    gemm_f16_kernel<<<dim3(24, 64), 256, GSMEM>>>(xhi, xlo, wq,
                                                  nullptr, 3 * DMODEL, 1);
    // 3) causal flash attention -> heads single fp16
    attn_f16_kernel<<<dim3(SEQ / 128, BH), 256, A_TOTAL>>>();

    // 4) output projection (1-term)
    gemm_f16_kernel<<<dim3(8, 64), 256, GSMEM>>>(hs, nullptr, wo,
                                                 out, DMODEL, 0);
}

// round 11
// speedup vs baseline: 2.1251x; 1.2114x over previous
#include <cuda_runtime.h>
#include <cuda_fp16.h>
#include <stdint.h>

// Problem constants
#define BATCH   4
#define HEADS   16
#define SEQ     2048
#define DK      64
#define DMODEL  1024
#define NTOK    (BATCH * SEQ)            // 8192
#define BH      (BATCH * HEADS)          // 64

// Scratch (device globals: cudaMalloc is forbidden)
__device__ __half g_x  [NTOK * DMODEL];          // x fp16
__device__ __half g_wq [3 * DMODEL * DMODEL];
__device__ __half g_wo [DMODEL * DMODEL];
__device__ __half g_q  [BH * SEQ * DK];          // Q fp16 (pre-scaled 1/8)
__device__ __half g_ks [BH * SEQ * DK];          // K fp16
__device__ __half g_vs [BH * SEQ * DK];          // V fp16
__device__ __half g_hs [NTOK * DMODEL];          // heads fp16

// ---------------------------------------------------------------------------
// Warp MMA + async-copy helpers (sm_80+ instructions only)
// ---------------------------------------------------------------------------
__device__ __forceinline__ uint32_t smem_u32(const void* p) {
    uint32_t a;
    asm("{ .reg .u64 t; cvta.to.shared.u64 t, %1; cvt.u32.u64 %0, t; }"
        : "=r"(a) : "l"(p));
    return a;
}
__device__ __forceinline__ void ldsm_x4(uint32_t& r0, uint32_t& r1,
                                        uint32_t& r2, uint32_t& r3, uint32_t addr) {
    asm volatile("ldmatrix.sync.aligned.m8n8.x4.shared.b16 {%0,%1,%2,%3}, [%4];"
                 : "=r"(r0), "=r"(r1), "=r"(r2), "=r"(r3) : "r"(addr));
}
__device__ __forceinline__ void ldsm_x4t(uint32_t& r0, uint32_t& r1,
                                         uint32_t& r2, uint32_t& r3, uint32_t addr) {
    asm volatile("ldmatrix.sync.aligned.m8n8.x4.trans.shared.b16 {%0,%1,%2,%3}, [%4];"
                 : "=r"(r0), "=r"(r1), "=r"(r2), "=r"(r3) : "r"(addr));
}
__device__ __forceinline__ void mma_f16(float* c, const uint32_t* a, const uint32_t* b) {
    asm volatile("mma.sync.aligned.m16n8k16.row.col.f32.f16.f16.f32 "
                 "{%0,%1,%2,%3}, {%4,%5,%6,%7}, {%8,%9}, {%0,%1,%2,%3};"
                 : "+f"(c[0]), "+f"(c[1]), "+f"(c[2]), "+f"(c[3])
                 : "r"(a[0]), "r"(a[1]), "r"(a[2]), "r"(a[3]),
                   "r"(b[0]), "r"(b[1]));
}
__device__ __forceinline__ uint32_t pack_f16(float a, float b) {
    __half2 h = __floats2half2_rn(a, b);
    return *(uint32_t*)&h;
}
__device__ __forceinline__ void cp16(uint32_t s, const void* g) {
    asm volatile("cp.async.cg.shared.global [%0], [%1], 16;" :: "r"(s), "l"(g));
}
#define CP_COMMIT() asm volatile("cp.async.commit_group;")
#define CP_WAIT1()  asm volatile("cp.async.wait_group 1;")

// ---------------------------------------------------------------------------
// fp32 -> fp16 round
// ---------------------------------------------------------------------------
__global__ __launch_bounds__(256)
void round_f16_kernel(const float4* __restrict__ src,
                      __half* __restrict__ dst, int n4)
{
    int i = blockIdx.x * blockDim.x + threadIdx.x;
    if (i >= n4) return;
    float4 v = src[i];
    *(__half2*)(dst + 4 * (size_t)i)     = __floats2half2_rn(v.x, v.y);
    *(__half2*)(dst + 4 * (size_t)i + 2) = __floats2half2_rn(v.z, v.w);
}

// ---------------------------------------------------------------------------
// fp16 GEMM on HMMA:  C[M,N] = A[M,K] * B[N,K]^T, K = 1024.
// 256 threads = 8 warps (2m x 4n), warp tile 64x32, BK=64.
// 3-stage cp.async ring, one barrier per k-chunk (16 chunks total).
// mode 0: fp32 store to C.  mode 1: QKV epilogue -> per-head fp16 planes
// (Q scaled 1/8).
// ---------------------------------------------------------------------------
#define BKS      64
#define NKI      (DMODEL / BKS)         // 16
#define GROW     144                    // 128B data + 16B pad per row
#define APLANE   (128 * GROW)           // 18432 bytes
#define STAGE_B2 (2 * APLANE)           // A, B
#define NSTG     3
#define GSMEM    (NSTG * STAGE_B2)      // 110592 bytes

__global__ __launch_bounds__(256, 1)
void gemm_f16_kernel(const __half* __restrict__ A,
                     const __half* __restrict__ B,
                     float* __restrict__ C, int N, int mode)
{
    extern __shared__ char smem[];
    const uint32_t sbase = smem_u32(smem);
    const int tid  = threadIdx.x;
    const int wid  = tid >> 5;
    const int lane = tid & 31;
    const int wm   = wid >> 2;          // 0..1  (64-row slab)
    const int wn   = wid & 3;           // 0..3  (32-col slab)
    const int m0   = blockIdx.y * 128;
    const int n0   = blockIdx.x * 128;
    const int K    = DMODEL;

    const __half* gA = A + (size_t)m0 * K;
    const __half* gB = B + (size_t)n0 * K;

    // cp.async: per stage 2 planes x 128 rows x 128B; 8 cp16 per thread
    const int r2 = tid >> 1;            // 0..127
    const int c4 = (tid & 1) * 4;       // 16B-chunk base (0 or 4)
    auto issue_stage = [&](int buf, int kc) {
        const uint32_t dst = sbase + buf * STAGE_B2 + r2 * GROW;
        const size_t goff = (size_t)r2 * K + kc;
#pragma unroll
        for (int j = 0; j < 4; ++j) {
            cp16(dst + (c4 + j) * 16,          gA + goff + (c4 + j) * 8);
            cp16(dst + APLANE + (c4 + j) * 16, gB + goff + (c4 + j) * 8);
        }
    };

    issue_stage(0, 0);      CP_COMMIT();
    issue_stage(1, BKS);    CP_COMMIT();

    float acc[4][4][4];
#pragma unroll
    for (int mi = 0; mi < 4; ++mi)
#pragma unroll
        for (int nj = 0; nj < 4; ++nj)
#pragma unroll
            for (int q = 0; q < 4; ++q) acc[mi][nj][q] = 0.0f;

    for (int kt = 0; kt < NKI; ++kt) {
        CP_WAIT1();            // chunk kt landed
        __syncthreads();       // all warps done with the buffer being refilled
        if (kt + 2 < NKI) {
            issue_stage((kt + 2) % NSTG, (kt + 2) * BKS);
            CP_COMMIT();
        }

        const uint32_t sb = sbase + (kt % NSTG) * STAGE_B2;
#pragma unroll
        for (int ks = 0; ks < 4; ++ks) {
            uint32_t a_[4][4], b[4][2];
#pragma unroll
            for (int mi = 0; mi < 4; ++mi) {
                const int row = wm * 64 + mi * 16 + (lane & 15);
                const uint32_t a = sb + row * GROW + ks * 32 + (lane >> 4) * 16;
                ldsm_x4(a_[mi][0], a_[mi][1], a_[mi][2], a_[mi][3], a);
            }
#pragma unroll
            for (int p2 = 0; p2 < 2; ++p2) {    // nj pair 2p2, 2p2+1
                const int row = wn * 32 + p2 * 16 + (lane & 15);
                const uint32_t a = sb + APLANE + row * GROW
                                 + ks * 32 + (lane >> 4) * 16;
                uint32_t r0, r1, r2x, r3;
                ldsm_x4(r0, r1, r2x, r3, a);
                b[2 * p2][0] = r0; b[2 * p2][1] = r2x;
                b[2 * p2 + 1][0] = r1; b[2 * p2 + 1][1] = r3;
            }
#pragma unroll
            for (int mi = 0; mi < 4; ++mi)
#pragma unroll
                for (int nj = 0; nj < 4; ++nj)
                    mma_f16(acc[mi][nj], a_[mi], b[nj]);
        }
    }

#pragma unroll
    for (int mi = 0; mi < 4; ++mi)
#pragma unroll
        for (int nj = 0; nj < 4; ++nj) {
            const int mrow = m0 + wm * 64 + mi * 16 + (lane >> 2);
            const int ncol = n0 + wn * 32 + nj * 8 + (lane & 3) * 2;
            if (mode == 0) {
                *(float2*)(C + (size_t)mrow * N + ncol) =
                    make_float2(acc[mi][nj][0], acc[mi][nj][1]);
                *(float2*)(C + (size_t)(mrow + 8) * N + ncol) =
                    make_float2(acc[mi][nj][2], acc[mi][nj][3]);
            } else {
                const int cc = ncol >> 10;
                const int h  = (ncol >> 6) & (HEADS - 1);
                const int dk = ncol & (DK - 1);
                const float scl = (cc == 0) ? 0.125f : 1.0f;
                __half* dstp = (cc == 0) ? g_q : ((cc == 1) ? g_ks : g_vs);
#pragma unroll
                for (int half_ = 0; half_ < 2; ++half_) {
                    const int m = mrow + half_ * 8;
                    const int b_ = m >> 11;
                    const int s  = m & (SEQ - 1);
                    const size_t off =
                        ((size_t)(b_ * HEADS + h) * SEQ + s) * DK + dk;
                    *(__half2*)(dstp + off) = __floats2half2_rn(
                        acc[mi][nj][half_ * 2] * scl,
                        acc[mi][nj][half_ * 2 + 1] * scl);
                }
            }
        }
}

// ---------------------------------------------------------------------------
// Causal flash attention on HMMA, fp16 1-term.
// Grid: (SEQ/128, BH). Block: 256 threads = 8 warps; warp owns 16 q-rows.
// KV tiles of 64 keys; next tile register-prefetched during compute.
// ---------------------------------------------------------------------------
#define ASTR   144                    // 64 fp16 = 128B data + 16 pad
#define A_Q    0
#define A_K    (128 * ASTR)
#define A_V    (A_K + 64 * ASTR)
#define A_TOTAL (A_V + 64 * ASTR)     // 36864 bytes

__global__ __launch_bounds__(256, 1)
void attn_f16_kernel()
{
    extern __shared__ char smem[];
    const uint32_t sb = smem_u32(smem);
    const int tid  = threadIdx.x;
    const int w    = tid >> 5;
    const int lane = tid & 31;
    const int qt   = blockIdx.x;          // 128-row q tile
    const int bh   = blockIdx.y;
    const int q0   = qt * 128;

    const __half* Qs = g_q  + ((size_t)bh * SEQ + q0) * DK;
    const __half* Ks = g_ks + (size_t)bh * SEQ * DK;
    const __half* Vs = g_vs + (size_t)bh * SEQ * DK;

    const int r_ = tid >> 3;              // 0..31
    const int c_ = tid & 7;               // 16B chunk

    // Load Q tile (128 x 64) + KV tile 0 into smem
#pragma unroll
    for (int t = 0; t < 4; ++t) {
        const int row = r_ + t * 32;
        *(uint4*)(smem + A_Q + row * ASTR + c_ * 16) =
            *(const uint4*)(Qs + (size_t)row * DK + c_ * 8);
    }
#pragma unroll
    for (int t = 0; t < 2; ++t) {
        const int row = r_ + t * 32;
        const size_t g = (size_t)row * DK + c_ * 8;
        const int so = row * ASTR + c_ * 16;
        *(uint4*)(smem + A_K + so) = *(const uint4*)(Ks + g);
        *(uint4*)(smem + A_V + so) = *(const uint4*)(Vs + g);
    }
    __syncthreads();

    // Q fragments (registers, whole kernel)
    uint32_t qf[4][4];
#pragma unroll
    for (int kk = 0; kk < 4; ++kk) {
        const int row = w * 16 + (lane & 15);
        const uint32_t a = sb + A_Q + row * ASTR + kk * 32 + (lane >> 4) * 16;
        ldsm_x4(qf[kk][0], qf[kk][1], qf[kk][2], qf[kk][3], a);
    }

    float o[8][4];
#pragma unroll
    for (int nj = 0; nj < 8; ++nj)
#pragma unroll
        for (int q = 0; q < 4; ++q) o[nj][q] = 0.0f;
    float mA = -1e30f, mB = -1e30f, lA = 0.0f, lB = 0.0f;

    const int nkt = 2 * qt + 2;
    for (int kt = 0; kt < nkt; ++kt) {
        // Prefetch next KV tile into registers
        uint4 pf[4];
        const bool havepf = (kt + 1 < nkt);
        if (havepf) {
#pragma unroll
            for (int t = 0; t < 2; ++t) {
                const int row = r_ + t * 32;
                const size_t g = (size_t)((kt + 1) * 64 + row) * DK + c_ * 8;
                pf[t * 2 + 0] = *(const uint4*)(Ks + g);
                pf[t * 2 + 1] = *(const uint4*)(Vs + g);
            }
        }

        // Warps 0-3 fully masked on the last diagonal tile
        if (!(kt == 2 * qt + 1 && w < 4)) {
            // ---- S = Q K^T (1 term) ----
            float s[8][4];
#pragma unroll
            for (int nj = 0; nj < 8; ++nj)
#pragma unroll
                for (int q = 0; q < 4; ++q) s[nj][q] = 0.0f;

#pragma unroll
            for (int kk = 0; kk < 4; ++kk) {
                uint32_t bk[8][2];
#pragma unroll
                for (int p2 = 0; p2 < 4; ++p2) {
                    const uint32_t a = sb + A_K + (p2 * 16 + (lane & 15)) * ASTR
                                     + kk * 32 + (lane >> 4) * 16;
                    uint32_t r0, r1, r2, r3;
                    ldsm_x4(r0, r1, r2, r3, a);
                    bk[2 * p2][0] = r0; bk[2 * p2][1] = r2;
                    bk[2 * p2 + 1][0] = r1; bk[2 * p2 + 1][1] = r3;
                }
#pragma unroll
                for (int nj = 0; nj < 8; ++nj)
                    mma_f16(s[nj], qf[kk], bk[nj]);
            }

            // ---- causal mask (diagonal tiles only) ----
            if (kt >= 2 * qt) {
                const int rowA = q0 + w * 16 + (lane >> 2);
                const int k0   = kt * 64;
#pragma unroll
                for (int nj = 0; nj < 8; ++nj) {
                    const int c0 = k0 + nj * 8 + (lane & 3) * 2;
                    if (c0 > rowA)     s[nj][0] = -1e30f;
                    if (c0 + 1 > rowA) s[nj][1] = -1e30f;
                    if (c0 > rowA + 8)     s[nj][2] = -1e30f;
                    if (c0 + 1 > rowA + 8) s[nj][3] = -1e30f;
                }
            }

            // ---- online softmax ----
            float tmA = -1e30f, tmB = -1e30f;
#pragma unroll
            for (int nj = 0; nj < 8; ++nj) {
                tmA = fmaxf(tmA, fmaxf(s[nj][0], s[nj][1]));
                tmB = fmaxf(tmB, fmaxf(s[nj][2], s[nj][3]));
            }
            tmA = fmaxf(tmA, __shfl_xor_sync(0xffffffffu, tmA, 1));
            tmA = fmaxf(tmA, __shfl_xor_sync(0xffffffffu, tmA, 2));
            tmB = fmaxf(tmB, __shfl_xor_sync(0xffffffffu, tmB, 1));
            tmB = fmaxf(tmB, __shfl_xor_sync(0xffffffffu, tmB, 2));
            const float mnA = fmaxf(mA, tmA);
            const float mnB = fmaxf(mB, tmB);
            const float fA = __expf(mA - mnA);
            const float fB = __expf(mB - mnB);
            mA = mnA; mB = mnB;

            float rsA = 0.0f, rsB = 0.0f;
#pragma unroll
            for (int nj = 0; nj < 8; ++nj) {
                s[nj][0] = __expf(s[nj][0] - mnA);
                s[nj][1] = __expf(s[nj][1] - mnA);
                s[nj][2] = __expf(s[nj][2] - mnB);
                s[nj][3] = __expf(s[nj][3] - mnB);
                rsA += s[nj][0] + s[nj][1];
                rsB += s[nj][2] + s[nj][3];
            }
            rsA += __shfl_xor_sync(0xffffffffu, rsA, 1);
            rsA += __shfl_xor_sync(0xffffffffu, rsA, 2);
            rsB += __shfl_xor_sync(0xffffffffu, rsB, 1);
            rsB += __shfl_xor_sync(0xffffffffu, rsB, 2);
            lA = lA * fA + rsA;
            lB = lB * fB + rsB;
#pragma unroll
            for (int nj = 0; nj < 8; ++nj) {
                o[nj][0] *= fA; o[nj][1] *= fA;
                o[nj][2] *= fB; o[nj][3] *= fB;
            }

            // ---- O += P V (1 term; P rounded to fp16) ----
#pragma unroll
            for (int kk = 0; kk < 4; ++kk) {
                const int j0 = 2 * kk, j1 = 2 * kk + 1;
                uint32_t ph[4];
                ph[0] = pack_f16(s[j0][0], s[j0][1]);
                ph[1] = pack_f16(s[j0][2], s[j0][3]);
                ph[2] = pack_f16(s[j1][0], s[j1][1]);
                ph[3] = pack_f16(s[j1][2], s[j1][3]);
#pragma unroll
                for (int p2 = 0; p2 < 4; ++p2) {
                    const uint32_t a = sb + A_V
                        + (kk * 16 + (lane & 7) + ((lane >> 3) & 1) * 8) * ASTR
                        + p2 * 32 + (lane >> 4) * 16;
                    uint32_t r0, r1, r2, r3;
                    ldsm_x4t(r0, r1, r2, r3, a);
                    uint32_t bv0[2] = {r0, r1}, bv1[2] = {r2, r3};
                    mma_f16(o[2 * p2],     ph, bv0);
                    mma_f16(o[2 * p2 + 1], ph, bv1);
                }
            }
        }

        if (havepf) {
            __syncthreads();
#pragma unroll
            for (int t = 0; t < 2; ++t) {
                const int row = r_ + t * 32;
                const int so = row * ASTR + c_ * 16;
                *(uint4*)(smem + A_K + so) = pf[t * 2 + 0];
                *(uint4*)(smem + A_V + so) = pf[t * 2 + 1];
            }
            __syncthreads();
        }
    }

    // ---- normalize + store heads [b*S+s][h*DK+dk] as fp16 ----
    const int b = bh >> 4;
    const int h = bh & 15;
    const float iA = 1.0f / lA;
    const float iB = 1.0f / lB;
    const int rowA = q0 + w * 16 + (lane >> 2);
#pragma unroll
    for (int nj = 0; nj < 8; ++nj) {
        const int col = h * DK + nj * 8 + (lane & 3) * 2;
        size_t off = (size_t)(b * SEQ + rowA) * DMODEL + col;
        *(__half2*)(g_hs + off) =
            __floats2half2_rn(o[nj][0] * iA, o[nj][1] * iA);
        *(__half2*)(g_hs + off + 8 * DMODEL) =
            __floats2half2_rn(o[nj][2] * iB, o[nj][3] * iB);
    }
}

// ---------------------------------------------------------------------------
extern "C" void kernel_launch(void* const* d_in, const int* in_sizes, int n_in,
                              void* d_out, int out_size)
{
    const float* x     = (const float*)d_in[0];
    const float* w_qkv = (const float*)d_in[1];
    const float* w_o   = (const float*)d_in[2];
    float* out = (float*)d_out;

    __half *xp, *wq, *wo, *hs;
    cudaGetSymbolAddress((void**)&xp, g_x);
    cudaGetSymbolAddress((void**)&wq, g_wq);
    cudaGetSymbolAddress((void**)&wo, g_wo);
    cudaGetSymbolAddress((void**)&hs, g_hs);

    cudaFuncSetAttribute(gemm_f16_kernel,
                         cudaFuncAttributeMaxDynamicSharedMemorySize, GSMEM);
    cudaFuncSetAttribute(attn_f16_kernel,
                         cudaFuncAttributeMaxDynamicSharedMemorySize, A_TOTAL);

    // 1) convert inputs to fp16
    round_f16_kernel<<<NTOK * DMODEL / 4 / 256, 256>>>((const float4*)x, xp,
                                                       NTOK * DMODEL / 4);
    round_f16_kernel<<<3 * DMODEL * DMODEL / 4 / 256, 256>>>((const float4*)w_qkv,
                                                             wq, 3 * DMODEL * DMODEL / 4);
    round_f16_kernel<<<DMODEL * DMODEL / 4 / 256, 256>>>((const float4*)w_o,
                                                         wo, DMODEL * DMODEL / 4);

    // 2) QKV projection -> per-head fp16 planes (Q pre-scaled 1/8)
    gemm_f16_kernel<<<dim3(24, 64), 256, GSMEM>>>(xp, wq, nullptr, 3 * DMODEL, 1);
    // 3) causal flash attention -> heads fp16
    attn_f16_kernel<<<dim3(SEQ / 128, BH), 256, A_TOTAL>>>();
    // 4) output projection
    gemm_f16_kernel<<<dim3(8, 64), 256, GSMEM>>>(hs, wo, out, DMODEL, 0);
}